// round 7
// baseline (speedup 1.0000x reference)
#include <cuda_runtime.h>

// Problem constants (fixed by the dataset)
#define kN 100000
#define kE 1600000
#define kG 256
// HID = 128 features = 32 float4 per row; kN % 32 == 0 (3125 tiles of 32 rows)

// ---------------- scratch (static device allocations; no cudaMalloc) ----------
__device__ float4 g_agg[kN * 32];   // 51.2 MB  mean-aggregated features
__device__ float4 g_h1 [kN * 32];   // 51.2 MB  layer-1 activations
__device__ int    g_deg[kN];
__device__ int    g_rowptr[kN + 1];
__device__ int    g_cursor[kN];
__device__ int    g_csr[kE];        // 6.4 MB   src indices grouped by dst
__device__ int    g_gcnt[kG];
__device__ float  g_gacc[kG];

// ---------------- f32x2 packed-math helpers (Blackwell) -----------------------
__device__ __forceinline__ unsigned long long pack2(float a, float b) {
    unsigned long long r;
    asm("mov.b64 %0, {%1, %2};" : "=l"(r) : "f"(a), "f"(b));
    return r;
}
__device__ __forceinline__ void unpack2(unsigned long long v, float &a, float &b) {
    asm("mov.b64 {%0, %1}, %2;" : "=f"(a), "=f"(b) : "l"(v));
}
__device__ __forceinline__ unsigned long long fma2(unsigned long long a,
                                                   unsigned long long b,
                                                   unsigned long long c) {
    unsigned long long d;
    asm("fma.rn.f32x2 %0, %1, %2, %3;" : "=l"(d) : "l"(a), "l"(b), "l"(c));
    return d;
}
__device__ __forceinline__ float fget(const float4& v, int c) {
    return c == 0 ? v.x : c == 1 ? v.y : c == 2 ? v.z : v.w;
}

// ---------------- CSR build ----------------------------------------------------
__global__ void k_zero_misc() {
    int i = blockIdx.x * blockDim.x + threadIdx.x;
    int stride = gridDim.x * blockDim.x;
    for (int j = i; j < kN; j += stride) g_deg[j] = 0;
    if (i < kG) { g_gcnt[i] = 0; g_gacc[i] = 0.f; }
}

// edge_index / batch are int32 on the wire (JAX x64 disabled).
__global__ void k_count(const int* __restrict__ ei,
                        const int* __restrict__ batch) {
    int t = blockIdx.x * blockDim.x + threadIdx.x;
    int stride = gridDim.x * blockDim.x;
    const int* dstp = ei + kE;
    for (int e = t; e < kE; e += stride) atomicAdd(&g_deg[dstp[e]], 1);
    for (int i = t; i < kN; i += stride) atomicAdd(&g_gcnt[batch[i]], 1);
}

// single-block exclusive scan of g_deg -> g_rowptr (and cursor copy)
__global__ void k_scan() {
    __shared__ int wsums[32];
    __shared__ int sbase;
    int tid = threadIdx.x, lane = tid & 31, w = tid >> 5;
    if (tid == 0) sbase = 0;
    __syncthreads();
    for (int base = 0; base < kN; base += 1024) {
        int i = base + tid;
        int v = (i < kN) ? g_deg[i] : 0;
        int x = v;
#pragma unroll
        for (int off = 1; off < 32; off <<= 1) {
            int y = __shfl_up_sync(0xffffffffu, x, off);
            if (lane >= off) x += y;
        }
        if (lane == 31) wsums[w] = x;
        __syncthreads();
        if (w == 0) {
            int s = wsums[lane];
#pragma unroll
            for (int off = 1; off < 32; off <<= 1) {
                int y = __shfl_up_sync(0xffffffffu, s, off);
                if (lane >= off) s += y;
            }
            wsums[lane] = s;
        }
        __syncthreads();
        int woff = (w > 0) ? wsums[w - 1] : 0;
        int incl = sbase + woff + x;           // inclusive prefix for index i
        if (i < kN) {
            g_rowptr[i + 1] = incl;
            g_cursor[i]     = incl - v;        // exclusive prefix
        }
        __syncthreads();
        if (tid == 1023) sbase = incl;         // chunk-carry
        __syncthreads();
    }
    if (tid == 0) g_rowptr[0] = 0;
}

__global__ void k_fill(const int* __restrict__ ei) {
    int t = blockIdx.x * blockDim.x + threadIdx.x;
    int stride = gridDim.x * blockDim.x;
    const int* srcp = ei;
    const int* dstp = ei + kE;
    for (int e = t; e < kE; e += stride) {
        int pos = atomicAdd(&g_cursor[dstp[e]], 1);
        g_csr[pos] = srcp[e];
    }
}

// ---------------- gather-based mean aggregation -------------------------------
// One warp per node: lanes cooperatively load 32 edge indices (coalesced),
// broadcast via shfl, each lane accumulates its own float4 column slice.
// Two accumulators (edge parity) break the FADD dependency chain.
__global__ void k_gather(const float4* __restrict__ feat_ext, int use_h1) {
    const float4* feat = use_h1 ? (const float4*)g_h1 : feat_ext;
    int gw   = (blockIdx.x * blockDim.x + threadIdx.x) >> 5;
    int lane = threadIdx.x & 31;
    int nw   = (gridDim.x * blockDim.x) >> 5;
    for (int node = gw; node < kN; node += nw) {
        int beg = g_rowptr[node];
        int end = g_rowptr[node + 1];
        float4 a0 = make_float4(0.f, 0.f, 0.f, 0.f);
        float4 a1 = make_float4(0.f, 0.f, 0.f, 0.f);
        for (int b = beg; b < end; b += 32) {
            int e = b + lane;
            int idx = (e < end) ? g_csr[e] : 0;
            int cnt = min(32, end - b);
            for (int i = 0; i < cnt - 1; i += 2) {
                int s0 = __shfl_sync(0xffffffffu, idx, i);
                int s1 = __shfl_sync(0xffffffffu, idx, i + 1);
                float4 v0 = __ldg(&feat[s0 * 32 + lane]);
                float4 v1 = __ldg(&feat[s1 * 32 + lane]);
                a0.x += v0.x; a0.y += v0.y; a0.z += v0.z; a0.w += v0.w;
                a1.x += v1.x; a1.y += v1.y; a1.z += v1.z; a1.w += v1.w;
            }
            if (cnt & 1) {
                int s0 = __shfl_sync(0xffffffffu, idx, cnt - 1);
                float4 v0 = __ldg(&feat[s0 * 32 + lane]);
                a0.x += v0.x; a0.y += v0.y; a0.z += v0.z; a0.w += v0.w;
            }
        }
        float di = 1.0f / (float)max(end - beg, 1);
        a0.x = (a0.x + a1.x) * di;
        a0.y = (a0.y + a1.y) * di;
        a0.z = (a0.z + a1.z) * di;
        a0.w = (a0.w + a1.w) * di;
        g_agg[node * 32 + lane] = a0;
    }
}

// ---------------- fused SAGE layer (FMA-bound tiling) --------------------------
// out_row = relu( agg_row @ Wl + b + x_row @ Wr )   (agg pre-scaled by 1/deg)
// CTA tile = 32 rows. Warp = 32 columns (lane = one column) x 16 rows.
//   warp w: colgroup = w&3 (cols 32*cg..), rowgroup = w>>2 (rows 16*rg..).
// Weights in SMEM, read as coalesced LDS.32 (128 B/warp/k, 1 crossbar phase).
// Features transposed into SMEM stage st[k][quad] (quad = 4 rows as float4,
// natural f32x2 row-pairs), stride 9 float4/k + XOR quad swizzle (k>>3)&7 so
// the transpose STS.128 is only ~4-way conflicted and compute reads are pure
// broadcast LDS.128. The swizzle spans all 8 quads, so tile boundaries use
// CTA-wide __syncthreads() (NOT per-half named barriers -- cross-half race).
// Inner loop per warp-k: 16 fma2 + 10 LDS + 2 movs -> FMA-pipe bound.
// POOL=true fuses readout: s = dot(h2_row, Wfc); gacc[batch[r]] += s.
#define KSTRIDE 9           // float4 units per k in the stage (8 quads + pad)
template <bool POOL>
__global__ void __launch_bounds__(256, 1)
k_layer(const float4* __restrict__ xin_ext, int use_h1,
        const float* __restrict__ Wl,
        const float* __restrict__ bias,
        const float* __restrict__ Wr,
        const int* __restrict__ batch,
        const float* __restrict__ Wfc) {
    extern __shared__ float smem[];
    float*  Wl_s = smem;                       // 64 KB
    float*  Wr_s = smem + 16384;               // 64 KB
    float4* st_a = (float4*)(smem + 32768);    // 128 * 9 float4 = 18 KB
    float4* st_x = st_a + 128 * KSTRIDE;       // 18 KB

    const float4* xin = use_h1 ? (const float4*)g_h1 : xin_ext;
    float* h1f = (float*)g_h1;

    {   // cooperative weight load ([k][n] row-major, same as global)
        const float4* wl4 = (const float4*)Wl;
        const float4* wr4 = (const float4*)Wr;
        float4* sl = (float4*)Wl_s;
        float4* sr = (float4*)Wr_s;
        for (int i = threadIdx.x; i < 4096; i += blockDim.x) {
            sl[i] = wl4[i];
            sr[i] = wr4[i];
        }
    }
    __syncthreads();

    int warp = threadIdx.x >> 5, lane = threadIdx.x & 31;
    int cg = warp & 3, rg = warp >> 2;
    int mycol = cg * 32 + lane;

    float bc = bias[mycol];
    unsigned long long binit = pack2(bc, bc);
    float wfcc = POOL ? Wfc[mycol] : 0.f;

    for (int tile = blockIdx.x; tile < kN / 32; tile += gridDim.x) {
        int tb = tile * 32;

        // ---- stage: warp w transposes rows 4w..4w+3 into quad w -------------
        {
            int r0 = tb + warp * 4;
            float4 a0 = g_agg[(r0 + 0) * 32 + lane];
            float4 a1 = g_agg[(r0 + 1) * 32 + lane];
            float4 a2 = g_agg[(r0 + 2) * 32 + lane];
            float4 a3 = g_agg[(r0 + 3) * 32 + lane];
            float4 x0 = xin[(r0 + 0) * 32 + lane];
            float4 x1 = xin[(r0 + 1) * 32 + lane];
            float4 x2 = xin[(r0 + 2) * 32 + lane];
            float4 x3 = xin[(r0 + 3) * 32 + lane];
#pragma unroll
            for (int c = 0; c < 4; c++) {
                int k = (lane << 2) + c;
                int phys = warp ^ ((k >> 3) & 7);
                st_a[k * KSTRIDE + phys] =
                    make_float4(fget(a0, c), fget(a1, c), fget(a2, c), fget(a3, c));
                st_x[k * KSTRIDE + phys] =
                    make_float4(fget(x0, c), fget(x1, c), fget(x2, c), fget(x3, c));
            }
        }
        __syncthreads();

        // ---- compute: lane = col mycol, rows rg*16 .. rg*16+15 --------------
        unsigned long long acc[8];
#pragma unroll
        for (int p = 0; p < 8; p++) acc[p] = binit;

        for (int kb = 0; kb < 128; kb += 8) {
            int swz = (kb >> 3) & 7;
            const float* wlp = Wl_s + kb * 128 + mycol;
            const float* wrp = Wr_s + kb * 128 + mycol;
            const ulonglong2* pa = (const ulonglong2*)(st_a + kb * KSTRIDE);
            const ulonglong2* px = (const ulonglong2*)(st_x + kb * KSTRIDE);
#pragma unroll
            for (int ku = 0; ku < 8; ku++) {
                float wl = wlp[ku * 128];
                float wr = wrp[ku * 128];
                unsigned long long wld = pack2(wl, wl);
                unsigned long long wrd = pack2(wr, wr);
#pragma unroll
                for (int qq = 0; qq < 4; qq++) {
                    int phys = (rg * 4 + qq) ^ swz;
                    ulonglong2 aq = pa[ku * KSTRIDE + phys];
                    ulonglong2 xq = px[ku * KSTRIDE + phys];
                    acc[2 * qq]     = fma2(aq.x, wld, acc[2 * qq]);
                    acc[2 * qq + 1] = fma2(aq.y, wld, acc[2 * qq + 1]);
                    acc[2 * qq]     = fma2(xq.x, wrd, acc[2 * qq]);
                    acc[2 * qq + 1] = fma2(xq.y, wrd, acc[2 * qq + 1]);
                }
            }
        }

        // ---- epilogue -------------------------------------------------------
#pragma unroll
        for (int p = 0; p < 8; p++) {
            float e0, e1;
            unpack2(acc[p], e0, e1);
            e0 = fmaxf(e0, 0.f);
            e1 = fmaxf(e1, 0.f);
            int rlo = tb + rg * 16 + (p >> 1) * 4 + (p & 1) * 2;
            if (!POOL) {
                h1f[(rlo + 0) * 128 + mycol] = e0;
                h1f[(rlo + 1) * 128 + mycol] = e1;
            } else {
                float s0 = e0 * wfcc, s1 = e1 * wfcc;
#pragma unroll
                for (int off = 16; off; off >>= 1) {
                    s0 += __shfl_xor_sync(0xffffffffu, s0, off);
                    s1 += __shfl_xor_sync(0xffffffffu, s1, off);
                }
                if (lane == 0) {
                    atomicAdd(&g_gacc[batch[rlo]],     s0);
                    atomicAdd(&g_gacc[batch[rlo + 1]], s1);
                }
            }
        }
        __syncthreads();
    }
}

__global__ void k_final(const float* __restrict__ bfc, float* __restrict__ out) {
    int g = threadIdx.x;
    if (g < kG) out[g] = g_gacc[g] / (float)max(g_gcnt[g], 1) + bfc[0];
}

// ---------------- entry point --------------------------------------------------
extern "C" void kernel_launch(void* const* d_in, const int* in_sizes, int n_in,
                              void* d_out, int out_size) {
    const float4* x     = (const float4*)d_in[0];
    const int*    ei    = (const int*)d_in[1];    // int32 (JAX x64 disabled)
    const int*    batch = (const int*)d_in[2];    // int32
    const float*  W1l   = (const float*)d_in[3];
    const float*  b1    = (const float*)d_in[4];
    const float*  W1r   = (const float*)d_in[5];
    const float*  W2l   = (const float*)d_in[6];
    const float*  b2    = (const float*)d_in[7];
    const float*  W2r   = (const float*)d_in[8];
    const float*  Wfc   = (const float*)d_in[9];
    const float*  bfc   = (const float*)d_in[10];
    float*        out   = (float*)d_out;

    // 128 KB weights + 36 KB stage = 164 KB dynamic smem
    const int smem = 2 * 65536 + 2 * 128 * KSTRIDE * 16;
    static int attr_done = 0;
    if (!attr_done) {
        cudaFuncSetAttribute(k_layer<false>,
                             cudaFuncAttributeMaxDynamicSharedMemorySize, smem);
        cudaFuncSetAttribute(k_layer<true>,
                             cudaFuncAttributeMaxDynamicSharedMemorySize, smem);
        attr_done = 1;
    }

    // CSR build (per call; deterministic)
    k_zero_misc<<<512, 256>>>();
    k_count<<<512, 256>>>(ei, batch);
    k_scan<<<1, 1024>>>();
    k_fill<<<512, 256>>>(ei);

    // Layer 1
    k_gather<<<1024, 256>>>(x, 0);
    k_layer<false><<<148, 256, smem>>>(x, 0, W1l, b1, W1r, batch, Wfc);

    // Layer 2 (+ fused global-mean-pool readout)
    k_gather<<<1024, 256>>>(x, 1);
    k_layer<true><<<148, 256, smem>>>(x, 1, W2l, b2, W2r, batch, Wfc);

    k_final<<<1, 256>>>(bfc, out);
}

// round 8
// speedup vs baseline: 1.2572x; 1.2572x over previous
#include <cuda_runtime.h>

// Problem constants (fixed by the dataset)
#define kN 100000
#define kE 1600000
#define kG 256
// HID = 128 features = 32 float4 per row

// ---------------- scratch (static device allocations; no cudaMalloc) ----------
__device__ float4 g_agg[kN * 32];   // 51.2 MB  mean-aggregated features
__device__ float4 g_h1 [kN * 32];   // 51.2 MB  layer-1 activations
__device__ int    g_deg[kN];
__device__ int    g_rowptr[kN + 1];
__device__ int    g_cursor[kN];
__device__ int    g_csr[kE];        // 6.4 MB   src indices grouped by dst
__device__ int    g_gcnt[kG];
__device__ float  g_gacc[kG];

// ---------------- f32x2 packed-math helpers (Blackwell) -----------------------
__device__ __forceinline__ unsigned long long pack2(float a, float b) {
    unsigned long long r;
    asm("mov.b64 %0, {%1, %2};" : "=l"(r) : "f"(a), "f"(b));
    return r;
}
__device__ __forceinline__ void unpack2(unsigned long long v, float &a, float &b) {
    asm("mov.b64 {%0, %1}, %2;" : "=f"(a), "=f"(b) : "l"(v));
}
__device__ __forceinline__ unsigned long long fma2(unsigned long long a,
                                                   unsigned long long b,
                                                   unsigned long long c) {
    unsigned long long d;
    asm("fma.rn.f32x2 %0, %1, %2, %3;" : "=l"(d) : "l"(a), "l"(b), "l"(c));
    return d;
}
__device__ __forceinline__ float fget(const float4& v, int c) {
    return c == 0 ? v.x : c == 1 ? v.y : c == 2 ? v.z : v.w;
}

// ---------------- CSR build ----------------------------------------------------
__global__ void k_zero_misc() {
    int i = blockIdx.x * blockDim.x + threadIdx.x;
    int stride = gridDim.x * blockDim.x;
    for (int j = i; j < kN; j += stride) g_deg[j] = 0;
    if (i < kG) { g_gcnt[i] = 0; g_gacc[i] = 0.f; }
}

// edge_index / batch are int32 on the wire (JAX x64 disabled).
__global__ void k_count(const int* __restrict__ ei,
                        const int* __restrict__ batch) {
    int t = blockIdx.x * blockDim.x + threadIdx.x;
    int stride = gridDim.x * blockDim.x;
    const int* dstp = ei + kE;
    for (int e = t; e < kE; e += stride) atomicAdd(&g_deg[dstp[e]], 1);
    for (int i = t; i < kN; i += stride) atomicAdd(&g_gcnt[batch[i]], 1);
}

// single-block exclusive scan of g_deg -> g_rowptr (and cursor copy)
__global__ void k_scan() {
    __shared__ int wsums[32];
    __shared__ int sbase;
    int tid = threadIdx.x, lane = tid & 31, w = tid >> 5;
    if (tid == 0) sbase = 0;
    __syncthreads();
    for (int base = 0; base < kN; base += 1024) {
        int i = base + tid;
        int v = (i < kN) ? g_deg[i] : 0;
        int x = v;
#pragma unroll
        for (int off = 1; off < 32; off <<= 1) {
            int y = __shfl_up_sync(0xffffffffu, x, off);
            if (lane >= off) x += y;
        }
        if (lane == 31) wsums[w] = x;
        __syncthreads();
        if (w == 0) {
            int s = wsums[lane];
#pragma unroll
            for (int off = 1; off < 32; off <<= 1) {
                int y = __shfl_up_sync(0xffffffffu, s, off);
                if (lane >= off) s += y;
            }
            wsums[lane] = s;
        }
        __syncthreads();
        int woff = (w > 0) ? wsums[w - 1] : 0;
        int incl = sbase + woff + x;           // inclusive prefix for index i
        if (i < kN) {
            g_rowptr[i + 1] = incl;
            g_cursor[i]     = incl - v;        // exclusive prefix
        }
        __syncthreads();
        if (tid == 1023) sbase = incl;         // chunk-carry
        __syncthreads();
    }
    if (tid == 0) g_rowptr[0] = 0;
}

__global__ void k_fill(const int* __restrict__ ei) {
    int t = blockIdx.x * blockDim.x + threadIdx.x;
    int stride = gridDim.x * blockDim.x;
    const int* srcp = ei;
    const int* dstp = ei + kE;
    for (int e = t; e < kE; e += stride) {
        int pos = atomicAdd(&g_cursor[dstp[e]], 1);
        g_csr[pos] = srcp[e];
    }
}

// ---------------- gather-based mean aggregation -------------------------------
// One warp per node: lanes cooperatively load 32 edge indices (coalesced),
// broadcast via shfl, each lane accumulates its own float4 column slice.
// Two accumulators (edge parity) break the FADD dependency chain.
__global__ void k_gather(const float4* __restrict__ feat_ext, int use_h1) {
    const float4* feat = use_h1 ? (const float4*)g_h1 : feat_ext;
    int gw   = (blockIdx.x * blockDim.x + threadIdx.x) >> 5;
    int lane = threadIdx.x & 31;
    int nw   = (gridDim.x * blockDim.x) >> 5;
    for (int node = gw; node < kN; node += nw) {
        int beg = g_rowptr[node];
        int end = g_rowptr[node + 1];
        float4 a0 = make_float4(0.f, 0.f, 0.f, 0.f);
        float4 a1 = make_float4(0.f, 0.f, 0.f, 0.f);
        for (int b = beg; b < end; b += 32) {
            int e = b + lane;
            int idx = (e < end) ? g_csr[e] : 0;
            int cnt = min(32, end - b);
            for (int i = 0; i < cnt - 1; i += 2) {
                int s0 = __shfl_sync(0xffffffffu, idx, i);
                int s1 = __shfl_sync(0xffffffffu, idx, i + 1);
                float4 v0 = __ldg(&feat[s0 * 32 + lane]);
                float4 v1 = __ldg(&feat[s1 * 32 + lane]);
                a0.x += v0.x; a0.y += v0.y; a0.z += v0.z; a0.w += v0.w;
                a1.x += v1.x; a1.y += v1.y; a1.z += v1.z; a1.w += v1.w;
            }
            if (cnt & 1) {
                int s0 = __shfl_sync(0xffffffffu, idx, cnt - 1);
                float4 v0 = __ldg(&feat[s0 * 32 + lane]);
                a0.x += v0.x; a0.y += v0.y; a0.z += v0.z; a0.w += v0.w;
            }
        }
        float di = 1.0f / (float)max(end - beg, 1);
        a0.x = (a0.x + a1.x) * di;
        a0.y = (a0.y + a1.y) * di;
        a0.z = (a0.z + a1.z) * di;
        a0.w = (a0.w + a1.w) * di;
        g_agg[node * 32 + lane] = a0;
    }
}

// ---------------- fused SAGE layer (independent warps, low-crossbar) ----------
// out_row = relu( agg_row @ Wl + b + x_row @ Wr )   (agg pre-scaled by 1/deg)
// Weights in SMEM [k][n] row-major (128 KB). Each warp independently processes
// 4 rows; lane owns columns {l, 32+l, 64+l, 96+l} as two f32x2 pairs, so
// weight reads are COALESCED LDS.32 (1 crossbar phase each).
// Features staged per-warp as dup f32x2 pairs at phys = f + 32*c (c = float4
// component, f = float4 slot): staging STS.64 is only 2-way conflicted, and
// compute reads fetch TWO k-steps per broadcast LDS.128 (k and k+4).
// Crossbar: 12 phases/warp-k (vs 24 in the naive mapping) -> ~96 cyc/SM-k
// against a 64-cyc fma2 floor. No cross-warp sync (no tile barriers).
// POOL=true fuses readout: s = dot(h2_row, Wfc); gacc[batch[r]] += s.
#define RPW 4               // rows per warp
template <bool POOL>
__global__ void __launch_bounds__(256, 1)
k_layer(const float4* __restrict__ xin_ext, int use_h1,
        const float* __restrict__ Wl,
        const float* __restrict__ bias,
        const float* __restrict__ Wr,
        const int* __restrict__ batch,
        const float* __restrict__ Wfc) {
    extern __shared__ float smem[];
    float* Wl_s = smem;                 // 64 KB
    float* Wr_s = smem + 16384;         // 64 KB
    // per-warp staging: [row][input][128 phys] ull = 8 KB/warp, 64 KB total
    unsigned long long* stage = (unsigned long long*)(smem + 32768);

    const float4* xin = use_h1 ? (const float4*)g_h1 : xin_ext;
    float* h1f = (float*)g_h1;

    {   // cooperative weight load ([k][n] row-major, same as global)
        const float4* wl4 = (const float4*)Wl;
        const float4* wr4 = (const float4*)Wr;
        float4* sl = (float4*)Wl_s;
        float4* sr = (float4*)Wr_s;
        for (int i = threadIdx.x; i < 4096; i += blockDim.x) {
            sl[i] = wl4[i];
            sr[i] = wr4[i];
        }
    }
    __syncthreads();

    int warp = threadIdx.x >> 5, lane = threadIdx.x & 31;
    unsigned long long* st = stage + warp * (RPW * 2 * 128);

    // bias / readout weights for this lane's columns {l,32+l,64+l,96+l}
    unsigned long long bp0 = pack2(bias[lane],      bias[32 + lane]);
    unsigned long long bp1 = pack2(bias[64 + lane], bias[96 + lane]);
    float wf0 = 0.f, wf1 = 0.f, wf2 = 0.f, wf3 = 0.f;
    if (POOL) {
        wf0 = Wfc[lane]; wf1 = Wfc[32 + lane];
        wf2 = Wfc[64 + lane]; wf3 = Wfc[96 + lane];
    }

    int gw = blockIdx.x * (blockDim.x >> 5) + warp;
    int nw = gridDim.x * (blockDim.x >> 5);
    int ngroups = (kN + RPW - 1) / RPW;

    for (int q = gw; q < ngroups; q += nw) {
        int r0 = q * RPW;
        __syncwarp();
        // ---- stage features: dup-pair of feature k=4f+c at phys=f+32c -------
#pragma unroll
        for (int j = 0; j < RPW; j++) {
            int r = r0 + j;
            float4 a, x;
            if (r < kN) {
                a = g_agg[r * 32 + lane];
                x = xin[r * 32 + lane];
            } else {
                a = make_float4(0.f, 0.f, 0.f, 0.f);
                x = a;
            }
            unsigned long long* sa = st + j * 256;        // input 0 (agg)
            unsigned long long* sx = sa + 128;            // input 1 (x)
#pragma unroll
            for (int c = 0; c < 4; c++) {
                sa[c * 32 + lane] = pack2(fget(a, c), fget(a, c));
                sx[c * 32 + lane] = pack2(fget(x, c), fget(x, c));
            }
        }
        __syncwarp();

        // ---- compute ---------------------------------------------------------
        unsigned long long acc0[RPW], acc1[RPW];
#pragma unroll
        for (int j = 0; j < RPW; j++) { acc0[j] = bp0; acc1[j] = bp1; }

#pragma unroll
        for (int c = 0; c < 4; c++) {
#pragma unroll 4
            for (int fp = 0; fp < 16; fp++) {
                int f0 = 2 * fp;
                int k0 = 4 * f0 + c;          // first k of the pair
                int k1 = k0 + 4;              // second k (f0+1)
                const float* wl0 = Wl_s + k0 * 128;
                const float* wl1 = Wl_s + k1 * 128;
                const float* wr0 = Wr_s + k0 * 128;
                const float* wr1 = Wr_s + k1 * 128;
                unsigned long long wl0p0 = pack2(wl0[lane],      wl0[32 + lane]);
                unsigned long long wl0p1 = pack2(wl0[64 + lane], wl0[96 + lane]);
                unsigned long long wl1p0 = pack2(wl1[lane],      wl1[32 + lane]);
                unsigned long long wl1p1 = pack2(wl1[64 + lane], wl1[96 + lane]);
                unsigned long long wr0p0 = pack2(wr0[lane],      wr0[32 + lane]);
                unsigned long long wr0p1 = pack2(wr0[64 + lane], wr0[96 + lane]);
                unsigned long long wr1p0 = pack2(wr1[lane],      wr1[32 + lane]);
                unsigned long long wr1p1 = pack2(wr1[64 + lane], wr1[96 + lane]);
#pragma unroll
                for (int j = 0; j < RPW; j++) {
                    const ulonglong2 av =
                        *(const ulonglong2*)(st + j * 256 + c * 32 + f0);
                    const ulonglong2 xv =
                        *(const ulonglong2*)(st + j * 256 + 128 + c * 32 + f0);
                    acc0[j] = fma2(av.x, wl0p0, acc0[j]);
                    acc1[j] = fma2(av.x, wl0p1, acc1[j]);
                    acc0[j] = fma2(av.y, wl1p0, acc0[j]);
                    acc1[j] = fma2(av.y, wl1p1, acc1[j]);
                    acc0[j] = fma2(xv.x, wr0p0, acc0[j]);
                    acc1[j] = fma2(xv.x, wr0p1, acc1[j]);
                    acc0[j] = fma2(xv.y, wr1p0, acc0[j]);
                    acc1[j] = fma2(xv.y, wr1p1, acc1[j]);
                }
            }
        }

        // ---- epilogue --------------------------------------------------------
#pragma unroll
        for (int j = 0; j < RPW; j++) {
            int r = r0 + j;
            if (r >= kN) continue;
            float o0, o1, o2, o3;      // cols l, 32+l, 64+l, 96+l
            unpack2(acc0[j], o0, o1);
            unpack2(acc1[j], o2, o3);
            o0 = fmaxf(o0, 0.f);
            o1 = fmaxf(o1, 0.f);
            o2 = fmaxf(o2, 0.f);
            o3 = fmaxf(o3, 0.f);
            if (!POOL) {
                h1f[r * 128 + lane]      = o0;
                h1f[r * 128 + 32 + lane] = o1;
                h1f[r * 128 + 64 + lane] = o2;
                h1f[r * 128 + 96 + lane] = o3;
            } else {
                float s = o0 * wf0 + o1 * wf1 + o2 * wf2 + o3 * wf3;
#pragma unroll
                for (int off = 16; off; off >>= 1)
                    s += __shfl_xor_sync(0xffffffffu, s, off);
                if (lane == 0) atomicAdd(&g_gacc[batch[r]], s);
            }
        }
    }
}

__global__ void k_final(const float* __restrict__ bfc, float* __restrict__ out) {
    int g = threadIdx.x;
    if (g < kG) out[g] = g_gacc[g] / (float)max(g_gcnt[g], 1) + bfc[0];
}

// ---------------- entry point --------------------------------------------------
extern "C" void kernel_launch(void* const* d_in, const int* in_sizes, int n_in,
                              void* d_out, int out_size) {
    const float4* x     = (const float4*)d_in[0];
    const int*    ei    = (const int*)d_in[1];    // int32 (JAX x64 disabled)
    const int*    batch = (const int*)d_in[2];    // int32
    const float*  W1l   = (const float*)d_in[3];
    const float*  b1    = (const float*)d_in[4];
    const float*  W1r   = (const float*)d_in[5];
    const float*  W2l   = (const float*)d_in[6];
    const float*  b2    = (const float*)d_in[7];
    const float*  W2r   = (const float*)d_in[8];
    const float*  Wfc   = (const float*)d_in[9];
    const float*  bfc   = (const float*)d_in[10];
    float*        out   = (float*)d_out;

    // 128 KB weights + 8 warps * 8 KB staging = 192 KB dynamic smem
    const int smem = 2 * 65536 + 8 * (RPW * 2 * 128) * 8;
    static int attr_done = 0;
    if (!attr_done) {
        cudaFuncSetAttribute(k_layer<false>,
                             cudaFuncAttributeMaxDynamicSharedMemorySize, smem);
        cudaFuncSetAttribute(k_layer<true>,
                             cudaFuncAttributeMaxDynamicSharedMemorySize, smem);
        attr_done = 1;
    }

    // CSR build (per call; deterministic)
    k_zero_misc<<<512, 256>>>();
    k_count<<<512, 256>>>(ei, batch);
    k_scan<<<1, 1024>>>();
    k_fill<<<512, 256>>>(ei);

    // Layer 1
    k_gather<<<1024, 256>>>(x, 0);
    k_layer<false><<<148, 256, smem>>>(x, 0, W1l, b1, W1r, batch, Wfc);

    // Layer 2 (+ fused global-mean-pool readout)
    k_gather<<<1024, 256>>>(x, 1);
    k_layer<true><<<148, 256, smem>>>(x, 1, W2l, b2, W2r, batch, Wfc);

    k_final<<<1, 256>>>(bfc, out);
}